// round 11
// baseline (speedup 1.0000x reference)
#include <cuda_runtime.h>

#define K_DIM 7168
#define E_DIM 256
#define BM 64
#define BN 64
#define BK 32
#define KC_TILES 10              // Eigen kc=320 floats = 10 tiles of BK=32
#define SMEM_BYTES (120 * 1024)  // force occupancy = 1 CTA/SM (2x120 > 228KB)

// packed f32x2 FMA (Blackwell): per-component IEEE rn fma
__device__ __forceinline__ unsigned long long ffma2(unsigned long long a,
                                                    unsigned long long b,
                                                    unsigned long long c) {
    unsigned long long d;
    asm("fma.rn.f32x2 %0, %1, %2, %3;" : "=l"(d) : "l"(a), "l"(b), "l"(c));
    return d;
}

__device__ __forceinline__ unsigned long long fadd2(unsigned long long a,
                                                    unsigned long long b) {
    unsigned long long d;
    asm("add.rn.f32x2 %0, %1, %2;" : "=l"(d) : "l"(a), "l"(b));
    return d;
}

// C[t, e] = sum_k A[t,k] * W[e,k] — fp32, Eigen-blocked accumulation order:
// c = ((0 + S_0) + S_1) + ... ; S_b = ascending-k fma partial over kc=320 block
// (last block = 128). BIT-EXACT match to XLA:CPU Eigen gemm — do not reorder.
//
// BM=64 x BN=64 tiles -> 1024 CTAs, occupancy forced to 1 -> 6.92 tiles/SM,
// 98.8% drain utilization (kills R8's 13.5% wave tail).
// Per thread: 4m x 2n, accumulators packed along m. A arrives as 2 packed
// pairs via one LDS.128; B is stored DUPLICATED in smem so one LDS.128 yields
// 2 dup-pairs -> zero dup-ALU in the inner loop (R10 lesson).
// XOR swizzle ((k>>2)&7)<<2 on smem columns -> conflict-free STS/LDS.
__global__ __launch_bounds__(512)
void moe_gemm_kernel(const float* __restrict__ A,
                     const float* __restrict__ W,
                     float* __restrict__ C, int T) {
    extern __shared__ char smem_raw[];
    // As[2][BK][64]  : A tile, element (k,m) at col m ^ sw(k)
    // Bd[2][BK][128] : B tile duplicated, expert n dup-pair at cols (2n)^sw(k), +1
    float (*As)[BK][BM] = reinterpret_cast<float (*)[BK][BM]>(smem_raw);
    float (*Bd)[BK][2 * BN] =
        reinterpret_cast<float (*)[BK][2 * BN]>(smem_raw + 2 * BK * BM * 4);

    const int tid = threadIdx.x;
    const int mg = tid & 15;    // m group: 4 tokens (16*4 = 64)
    const int ng = tid >> 4;    // n group: 2 experts (32*2 = 64)
    const int n0 = blockIdx.x * BN;   // grid.x = 4 n-tiles (fast -> A L2 reuse)
    const int m0 = blockIdx.y * BM;   // grid.y = 256 m-tiles

    // loaders: 8 threads per row, one float4 (64 rows x 32 k each for A and B)
    const int lr = tid >> 3;             // row 0..63
    const int lc = (tid & 7) * 4;        // k offset 0,4,...,28
    const int lsw = (tid & 7) << 2;      // swizzle for this thread's k-group
    const float* Abase = A + (size_t)(m0 + lr) * K_DIM + lc;
    const float* Wbase = W + (size_t)(n0 + lr) * K_DIM + lc;

    const int acolA = lr ^ lsw;          // swizzled store col in As
    const int acolB = (2 * lr) ^ lsw;    // swizzled store col in Bd

    unsigned long long acc[2][2], bac[2][2];  // [n][m-pair]
#pragma unroll
    for (int n = 0; n < 2; ++n)
#pragma unroll
        for (int p = 0; p < 2; ++p) { acc[n][p] = 0ull; bac[n][p] = 0ull; }

    float4 aP = *reinterpret_cast<const float4*>(Abase);
    float4 bP = *reinterpret_cast<const float4*>(Wbase);

    const int nIter = K_DIM / BK;  // 224
    for (int kt = 0; kt < nIter; ++kt) {
        const int buf = kt & 1;
        As[buf][lc + 0][acolA] = aP.x;
        As[buf][lc + 1][acolA] = aP.y;
        As[buf][lc + 2][acolA] = aP.z;
        As[buf][lc + 3][acolA] = aP.w;
        *reinterpret_cast<float2*>(&Bd[buf][lc + 0][acolB]) = make_float2(bP.x, bP.x);
        *reinterpret_cast<float2*>(&Bd[buf][lc + 1][acolB]) = make_float2(bP.y, bP.y);
        *reinterpret_cast<float2*>(&Bd[buf][lc + 2][acolB]) = make_float2(bP.z, bP.z);
        *reinterpret_cast<float2*>(&Bd[buf][lc + 3][acolB]) = make_float2(bP.w, bP.w);
        __syncthreads();

        if (kt + 1 < nIter) {
            aP = *reinterpret_cast<const float4*>(Abase + (size_t)(kt + 1) * BK);
            bP = *reinterpret_cast<const float4*>(Wbase + (size_t)(kt + 1) * BK);
        }

#pragma unroll
        for (int k = 0; k < BK; ++k) {
            const int sw = ((k >> 2) & 7) << 2;
            // A: 4 m-floats = 2 packed pairs (m0+4mg .. +3)
            ulonglong2 ap = *reinterpret_cast<const ulonglong2*>(
                &As[buf][k][(mg * 4) ^ sw]);
            // B: dup pairs for experts 2ng, 2ng+1
            ulonglong2 bp = *reinterpret_cast<const ulonglong2*>(
                &Bd[buf][k][(ng * 4) ^ sw]);
            bac[0][0] = ffma2(ap.x, bp.x, bac[0][0]);
            bac[0][1] = ffma2(ap.y, bp.x, bac[0][1]);
            bac[1][0] = ffma2(ap.x, bp.y, bac[1][0]);
            bac[1][1] = ffma2(ap.y, bp.y, bac[1][1]);
        }

        // Eigen kc=320 block boundary: c += S_b; S_b = 0
        if (((kt + 1) % KC_TILES) == 0) {
#pragma unroll
            for (int n = 0; n < 2; ++n)
#pragma unroll
                for (int p = 0; p < 2; ++p) {
                    acc[n][p] = fadd2(acc[n][p], bac[n][p]);
                    bac[n][p] = 0ull;
                }
        }
    }

    // final (remainder 128-wide) block flush
#pragma unroll
    for (int n = 0; n < 2; ++n)
#pragma unroll
        for (int p = 0; p < 2; ++p)
            acc[n][p] = fadd2(acc[n][p], bac[n][p]);

    // epilogue: acc[n][p] component c -> C[m0+4mg+2p+c][n0+2ng+n]
#pragma unroll
    for (int p = 0; p < 2; ++p) {
        float2 f0 = *reinterpret_cast<float2*>(&acc[0][p]);
        float2 f1 = *reinterpret_cast<float2*>(&acc[1][p]);
        int mb = m0 + mg * 4 + p * 2;
        float* c0 = C + (size_t)mb * E_DIM + n0 + ng * 2;
        float* c1 = C + (size_t)(mb + 1) * E_DIM + n0 + ng * 2;
        *reinterpret_cast<float2*>(c0) = make_float2(f0.x, f1.x);
        *reinterpret_cast<float2*>(c1) = make_float2(f0.y, f1.y);
    }
}

// XLA EmitFastTanh replica — UNFUSED mul/add Horner (CPU LLVM does not
// contract), IEEE fdiv, clamp +-7.90531110763549805, |x|<0.0004 -> x.
__device__ __forceinline__ float xla_tanhf_nofma(float x) {
    float xc = fminf(fmaxf(x, -7.90531110763549805f), 7.90531110763549805f);
    float x2 = __fmul_rn(xc, xc);
    float np = -2.76076847742355e-16f;
    np = __fadd_rn(__fmul_rn(x2, np),  2.00018790482477e-13f);
    np = __fadd_rn(__fmul_rn(x2, np), -8.60467152213735e-11f);
    np = __fadd_rn(__fmul_rn(x2, np),  5.12229709037114e-08f);
    np = __fadd_rn(__fmul_rn(x2, np),  1.48572235717979e-05f);
    np = __fadd_rn(__fmul_rn(x2, np),  6.37261928875436e-04f);
    np = __fadd_rn(__fmul_rn(x2, np),  4.89352455891786e-03f);
    float num = __fmul_rn(xc, np);
    float dp = 1.19825839466702e-06f;
    dp = __fadd_rn(__fmul_rn(x2, dp), 1.18534705686654e-04f);
    dp = __fadd_rn(__fmul_rn(x2, dp), 2.26843463243900e-03f);
    dp = __fadd_rn(__fmul_rn(x2, dp), 4.89352518554385e-03f);
    float r = __fdiv_rn(num, dp);
    return (fabsf(x) < 0.0004f) ? x : r;
}

// XLA logistic: 0.5 + 0.5 * tanh(0.5 * x), unfused.
__device__ __forceinline__ float sigmoid_xla(float x) {
    float t = xla_tanhf_nofma(__fmul_rn(0.5f, x));
    return __fadd_rn(0.5f, __fmul_rn(0.5f, t));
}

// one warp per token
__global__ void moe_router_kernel(const float* __restrict__ logits,
                                  float* __restrict__ outW,
                                  float* __restrict__ outI, int T) {
    const unsigned FULL = 0xFFFFFFFFu;
    int warp = (blockIdx.x * blockDim.x + threadIdx.x) >> 5;
    int lane = threadIdx.x & 31;
    if (warp >= T) return;

    const float* row = logits + (size_t)warp * E_DIM;
    float4 v0 = *reinterpret_cast<const float4*>(row + lane * 8);
    float4 v1 = *reinterpret_cast<const float4*>(row + lane * 8 + 4);

    float s[8];
    s[0] = sigmoid_xla(v0.x); s[1] = sigmoid_xla(v0.y);
    s[2] = sigmoid_xla(v0.z); s[3] = sigmoid_xla(v0.w);
    s[4] = sigmoid_xla(v1.x); s[5] = sigmoid_xla(v1.y);
    s[6] = sigmoid_xla(v1.z); s[7] = sigmoid_xla(v1.w);

    // group sum over 32 experts (butterfly tree)
    float f[8];
#pragma unroll
    for (int j = 0; j < 8; ++j)
        f[j] = s[j] + __shfl_xor_sync(FULL, s[j], 2);
    float g[8];
#pragma unroll
    for (int j = 0; j < 8; ++j)
        g[j] = f[j] + __shfl_xor_sync(FULL, f[j], 1);
    float h0 = g[0] + g[4];
    float h1 = g[1] + g[5];
    float h2 = g[2] + g[6];
    float h3 = g[3] + g[7];
    float p0 = h0 + h2;
    float p1 = h1 + h3;
    float mygs = p0 + p1;     // group sum for group (lane>>2)
    int myg = lane >> 2;

    // rank of my group among 8 groups (ties -> lower index, jax top_k)
    int rank = 0;
#pragma unroll
    for (int h = 0; h < 8; ++h) {
        float gh = __shfl_sync(FULL, mygs, h * 4);
        if (h != myg && (gh > mygs || (gh == mygs && h < myg))) rank++;
    }
    bool sel = (rank < 4);

    float ms[8];
#pragma unroll
    for (int j = 0; j < 8; ++j) ms[j] = sel ? s[j] : 0.0f;

    float topv[8];
    int topi[8];
#pragma unroll
    for (int it = 0; it < 8; ++it) {
        float bv = -1.0f;
        int bi = 0;
#pragma unroll
        for (int j = 0; j < 8; ++j) {
            if (ms[j] > bv) { bv = ms[j]; bi = lane * 8 + j; }
        }
#pragma unroll
        for (int off = 16; off; off >>= 1) {
            float ov = __shfl_xor_sync(FULL, bv, off);
            int oi = __shfl_xor_sync(FULL, bi, off);
            if (ov > bv || (ov == bv && oi < bi)) { bv = ov; bi = oi; }
        }
        topv[it] = bv;
        topi[it] = bi;
        if ((bi >> 3) == lane) ms[bi & 7] = -1.0f;
    }

    float denom = 0.f;
#pragma unroll
    for (int it = 0; it < 8; ++it) denom += topv[it];
    denom = fmaxf(denom, 1e-12f);

    if (lane < 8) {
        outW[(size_t)warp * 8 + lane] = __fdiv_rn(topv[lane], denom);
        outI[(size_t)warp * 8 + lane] = (float)topi[lane];
    }
}

extern "C" void kernel_launch(void* const* d_in, const int* in_sizes, int n_in,
                              void* d_out, int out_size) {
    const float* H = (const float*)d_in[0];   // [T, 7168] fp32
    const float* W = (const float*)d_in[1];   // [256, 7168] fp32
    float* out = (float*)d_out;

    int T = in_sizes[0] / K_DIM;

    // output layout: [T*8 weights][T*8 indices][T*256 logits]
    float* outW = out;
    float* outI = out + (size_t)T * 8;
    float* logits = out + (size_t)T * 16;

    cudaFuncSetAttribute(moe_gemm_kernel,
                         cudaFuncAttributeMaxDynamicSharedMemorySize, SMEM_BYTES);

    // grid.x = 4 n-tiles fastest: live window = 37 m-tiles (66MB) -> A in L2
    dim3 grid(E_DIM / BN, T / BM);
    moe_gemm_kernel<<<grid, 512, SMEM_BYTES>>>(H, W, logits, T);

    int warps = T;
    int threads = 256;
    int blocks = (warps * 32 + threads - 1) / threads;
    moe_router_kernel<<<blocks, threads>>>(logits, outW, outI, T);
}

// round 12
// speedup vs baseline: 1.3418x; 1.3418x over previous
#include <cuda_runtime.h>

#define K_DIM 7168
#define E_DIM 256
#define BM 128
#define BN 32
#define BK 16
#define KC_TILES 20              // Eigen kc=320 floats = 20 tiles of BK=16
#define SMEM_BYTES (120 * 1024)  // forces occupancy = 1 CTA/SM

// packed f32x2 FMA (Blackwell): per-component IEEE rn fma
__device__ __forceinline__ unsigned long long ffma2(unsigned long long a,
                                                    unsigned long long b,
                                                    unsigned long long c) {
    unsigned long long d;
    asm("fma.rn.f32x2 %0, %1, %2, %3;" : "=l"(d) : "l"(a), "l"(b), "l"(c));
    return d;
}

__device__ __forceinline__ unsigned long long fadd2(unsigned long long a,
                                                    unsigned long long b) {
    unsigned long long d;
    asm("add.rn.f32x2 %0, %1, %2;" : "=l"(d) : "l"(a), "l"(b));
    return d;
}

__device__ __forceinline__ unsigned long long dup_f32(float a) {
    unsigned long long p;
    asm("mov.b64 %0, {%1, %1};" : "=l"(p) : "r"(__float_as_uint(a)));
    return p;
}

// C[t, e] = sum_k A[t,k] * W[e,k] — fp32, Eigen-blocked accumulation order:
// c = ((0 + S_0) + S_1) + ... ; S_b = ascending-k fma partial over kc=320 block
// (last block = 128). BIT-EXACT match to XLA:CPU Eigen gemm — do not reorder.
//
// BM=128 x BN=32 -> 1024 tiles, occupancy FORCED to 1 (120KB smem request)
// -> x = 6.92 tiles/SM -> 1.2% drain waste (vs R8's 13.5% two-wave tail).
// 256 threads, 8m x 2n per thread: 8 FFMA2 + 8 dup + 3 LDS per thread-k,
// k-linear smem addressing, fragment double-buffer bridges LDS latency at
// 2 warps/SMSP. n-fastest grid -> live A window 18.5 m-tiles = 68MB < L2.
__global__ __launch_bounds__(256)
void moe_gemm_kernel(const float* __restrict__ A,
                     const float* __restrict__ W,
                     float* __restrict__ C, int T) {
    extern __shared__ char smem_raw[];
    float (*As)[BK][BM] = reinterpret_cast<float (*)[BK][BM]>(smem_raw);
    float (*Bs)[BK][BN] =
        reinterpret_cast<float (*)[BK][BN]>(smem_raw + 2 * BK * BM * 4);

    const int tid = threadIdx.x;
    const int tx = tid & 15;   // n: 2 experts per thread (16*2 = 32)
    const int ty = tid >> 4;   // m: 8 tokens per thread  (16*8 = 128)
    const int n0 = blockIdx.x * BN;   // grid.x = 8 n-tiles (fast: A L2 reuse)
    const int m0 = blockIdx.y * BM;   // grid.y = 128 m-tiles

    // A loader: 2 threads per row, 8 floats (2x float4) each  (128 x 16)
    const int alr = tid >> 1;
    const int alc = (tid & 1) * 8;
    const float* Abase = A + (size_t)(m0 + alr) * K_DIM + alc;
    // B loader: 8 threads per row, one float2 each  (32 x 16)
    const int blr = tid >> 3;
    const int blc = (tid & 7) * 2;
    const float* Wbase = W + (size_t)(n0 + blr) * K_DIM + blc;

    unsigned long long acc[8], bac[8];   // [m] each packs 2 n's
#pragma unroll
    for (int i = 0; i < 8; ++i) { acc[i] = 0ull; bac[i] = 0ull; }

    float4 aP0 = *reinterpret_cast<const float4*>(Abase);
    float4 aP1 = *reinterpret_cast<const float4*>(Abase + 4);
    float2 bP  = *reinterpret_cast<const float2*>(Wbase);

    const int nIter = K_DIM / BK;  // 448
    for (int kt = 0; kt < nIter; ++kt) {
        const int buf = kt & 1;
        As[buf][alc + 0][alr] = aP0.x; As[buf][alc + 1][alr] = aP0.y;
        As[buf][alc + 2][alr] = aP0.z; As[buf][alc + 3][alr] = aP0.w;
        As[buf][alc + 4][alr] = aP1.x; As[buf][alc + 5][alr] = aP1.y;
        As[buf][alc + 6][alr] = aP1.z; As[buf][alc + 7][alr] = aP1.w;
        Bs[buf][blc + 0][blr] = bP.x;  Bs[buf][blc + 1][blr] = bP.y;
        __syncthreads();

        // prefetch next tile from global (hidden under compute below)
        if (kt + 1 < nIter) {
            const float* an = Abase + (size_t)(kt + 1) * BK;
            const float* wn = Wbase + (size_t)(kt + 1) * BK;
            aP0 = *reinterpret_cast<const float4*>(an);
            aP1 = *reinterpret_cast<const float4*>(an + 4);
            bP  = *reinterpret_cast<const float2*>(wn);
        }

        // fragment double-buffer: load k=0, then rotate k+1 under k's FMAs
        float4 a0 = *reinterpret_cast<const float4*>(&As[buf][0][ty * 8]);
        float4 a1 = *reinterpret_cast<const float4*>(&As[buf][0][ty * 8 + 4]);
        unsigned long long pb =
            *reinterpret_cast<const unsigned long long*>(&Bs[buf][0][tx * 2]);
#pragma unroll
        for (int k = 0; k < BK; ++k) {
            float4 na0, na1;
            unsigned long long npb;
            if (k + 1 < BK) {
                na0 = *reinterpret_cast<const float4*>(&As[buf][k + 1][ty * 8]);
                na1 = *reinterpret_cast<const float4*>(&As[buf][k + 1][ty * 8 + 4]);
                npb = *reinterpret_cast<const unsigned long long*>(
                    &Bs[buf][k + 1][tx * 2]);
            }
            float av[8] = {a0.x, a0.y, a0.z, a0.w, a1.x, a1.y, a1.z, a1.w};
#pragma unroll
            for (int i = 0; i < 8; ++i)
                bac[i] = ffma2(dup_f32(av[i]), pb, bac[i]);
            if (k + 1 < BK) { a0 = na0; a1 = na1; pb = npb; }
        }

        // Eigen kc=320 block boundary: c += S_b; S_b = 0
        if (((kt + 1) % KC_TILES) == 0) {
#pragma unroll
            for (int i = 0; i < 8; ++i) {
                acc[i] = fadd2(acc[i], bac[i]);
                bac[i] = 0ull;
            }
        }
    }

    // final (remainder 128-wide) block flush
#pragma unroll
    for (int i = 0; i < 8; ++i) acc[i] = fadd2(acc[i], bac[i]);

    // epilogue: acc[i] = (e0,e1) for token m0+ty*8+i, experts n0+tx*2,+1
#pragma unroll
    for (int i = 0; i < 8; ++i) {
        int m = m0 + ty * 8 + i;
        float2 v = *reinterpret_cast<float2*>(&acc[i]);
        *reinterpret_cast<float2*>(C + (size_t)m * E_DIM + n0 + tx * 2) = v;
    }
}

// XLA EmitFastTanh replica — UNFUSED mul/add Horner (CPU LLVM does not
// contract), IEEE fdiv, clamp +-7.90531110763549805, |x|<0.0004 -> x.
__device__ __forceinline__ float xla_tanhf_nofma(float x) {
    float xc = fminf(fmaxf(x, -7.90531110763549805f), 7.90531110763549805f);
    float x2 = __fmul_rn(xc, xc);
    float np = -2.76076847742355e-16f;
    np = __fadd_rn(__fmul_rn(x2, np),  2.00018790482477e-13f);
    np = __fadd_rn(__fmul_rn(x2, np), -8.60467152213735e-11f);
    np = __fadd_rn(__fmul_rn(x2, np),  5.12229709037114e-08f);
    np = __fadd_rn(__fmul_rn(x2, np),  1.48572235717979e-05f);
    np = __fadd_rn(__fmul_rn(x2, np),  6.37261928875436e-04f);
    np = __fadd_rn(__fmul_rn(x2, np),  4.89352455891786e-03f);
    float num = __fmul_rn(xc, np);
    float dp = 1.19825839466702e-06f;
    dp = __fadd_rn(__fmul_rn(x2, dp), 1.18534705686654e-04f);
    dp = __fadd_rn(__fmul_rn(x2, dp), 2.26843463243900e-03f);
    dp = __fadd_rn(__fmul_rn(x2, dp), 4.89352518554385e-03f);
    float r = __fdiv_rn(num, dp);
    return (fabsf(x) < 0.0004f) ? x : r;
}

// XLA logistic: 0.5 + 0.5 * tanh(0.5 * x), unfused.
__device__ __forceinline__ float sigmoid_xla(float x) {
    float t = xla_tanhf_nofma(__fmul_rn(0.5f, x));
    return __fadd_rn(0.5f, __fmul_rn(0.5f, t));
}

// one warp per token
__global__ void moe_router_kernel(const float* __restrict__ logits,
                                  float* __restrict__ outW,
                                  float* __restrict__ outI, int T) {
    const unsigned FULL = 0xFFFFFFFFu;
    int warp = (blockIdx.x * blockDim.x + threadIdx.x) >> 5;
    int lane = threadIdx.x & 31;
    if (warp >= T) return;

    const float* row = logits + (size_t)warp * E_DIM;
    float4 v0 = *reinterpret_cast<const float4*>(row + lane * 8);
    float4 v1 = *reinterpret_cast<const float4*>(row + lane * 8 + 4);

    float s[8];
    s[0] = sigmoid_xla(v0.x); s[1] = sigmoid_xla(v0.y);
    s[2] = sigmoid_xla(v0.z); s[3] = sigmoid_xla(v0.w);
    s[4] = sigmoid_xla(v1.x); s[5] = sigmoid_xla(v1.y);
    s[6] = sigmoid_xla(v1.z); s[7] = sigmoid_xla(v1.w);

    // group sum over 32 experts (butterfly tree)
    float f[8];
#pragma unroll
    for (int j = 0; j < 8; ++j)
        f[j] = s[j] + __shfl_xor_sync(FULL, s[j], 2);
    float g[8];
#pragma unroll
    for (int j = 0; j < 8; ++j)
        g[j] = f[j] + __shfl_xor_sync(FULL, f[j], 1);
    float h0 = g[0] + g[4];
    float h1 = g[1] + g[5];
    float h2 = g[2] + g[6];
    float h3 = g[3] + g[7];
    float p0 = h0 + h2;
    float p1 = h1 + h3;
    float mygs = p0 + p1;     // group sum for group (lane>>2)
    int myg = lane >> 2;

    // rank of my group among 8 groups (ties -> lower index, jax top_k)
    int rank = 0;
#pragma unroll
    for (int h = 0; h < 8; ++h) {
        float gh = __shfl_sync(FULL, mygs, h * 4);
        if (h != myg && (gh > mygs || (gh == mygs && h < myg))) rank++;
    }
    bool sel = (rank < 4);

    float ms[8];
#pragma unroll
    for (int j = 0; j < 8; ++j) ms[j] = sel ? s[j] : 0.0f;

    float topv[8];
    int topi[8];
#pragma unroll
    for (int it = 0; it < 8; ++it) {
        float bv = -1.0f;
        int bi = 0;
#pragma unroll
        for (int j = 0; j < 8; ++j) {
            if (ms[j] > bv) { bv = ms[j]; bi = lane * 8 + j; }
        }
#pragma unroll
        for (int off = 16; off; off >>= 1) {
            float ov = __shfl_xor_sync(FULL, bv, off);
            int oi = __shfl_xor_sync(FULL, bi, off);
            if (ov > bv || (ov == bv && oi < bi)) { bv = ov; bi = oi; }
        }
        topv[it] = bv;
        topi[it] = bi;
        if ((bi >> 3) == lane) ms[bi & 7] = -1.0f;
    }

    float denom = 0.f;
#pragma unroll
    for (int it = 0; it < 8; ++it) denom += topv[it];
    denom = fmaxf(denom, 1e-12f);

    if (lane < 8) {
        outW[(size_t)warp * 8 + lane] = __fdiv_rn(topv[lane], denom);
        outI[(size_t)warp * 8 + lane] = (float)topi[lane];
    }
}

extern "C" void kernel_launch(void* const* d_in, const int* in_sizes, int n_in,
                              void* d_out, int out_size) {
    const float* H = (const float*)d_in[0];   // [T, 7168] fp32
    const float* W = (const float*)d_in[1];   // [256, 7168] fp32
    float* out = (float*)d_out;

    int T = in_sizes[0] / K_DIM;

    // output layout: [T*8 weights][T*8 indices][T*256 logits]
    float* outW = out;
    float* outI = out + (size_t)T * 8;
    float* logits = out + (size_t)T * 16;

    cudaFuncSetAttribute(moe_gemm_kernel,
                         cudaFuncAttributeMaxDynamicSharedMemorySize, SMEM_BYTES);

    // n-fastest: 148 live CTAs span 18.5 m-tiles (68MB) -> A re-reads hit L2
    dim3 grid(E_DIM / BN, T / BM);
    moe_gemm_kernel<<<grid, 256, SMEM_BYTES>>>(H, W, logits, T);

    int warps = T;
    int threads = 256;
    int blocks = (warps * 32 + threads - 1) / threads;
    moe_router_kernel<<<blocks, threads>>>(logits, outW, outI, T);
}

// round 13
// speedup vs baseline: 1.5057x; 1.1221x over previous
#include <cuda_runtime.h>

#define K_DIM 7168
#define E_DIM 256
#define BM 64
#define BN 32
#define BK 16
#define KC_TILES 20   // Eigen kc=320 floats = 20 tiles of BK=16

// packed f32x2 FMA (Blackwell): per-component IEEE rn fma
__device__ __forceinline__ unsigned long long ffma2(unsigned long long a,
                                                    unsigned long long b,
                                                    unsigned long long c) {
    unsigned long long d;
    asm("fma.rn.f32x2 %0, %1, %2, %3;" : "=l"(d) : "l"(a), "l"(b), "l"(c));
    return d;
}

__device__ __forceinline__ unsigned long long fadd2(unsigned long long a,
                                                    unsigned long long b) {
    unsigned long long d;
    asm("add.rn.f32x2 %0, %1, %2;" : "=l"(d) : "l"(a), "l"(b));
    return d;
}

__device__ __forceinline__ unsigned long long dup_f32(float a) {
    unsigned long long p;
    asm("mov.b64 %0, {%1, %1};" : "=l"(p) : "r"(__float_as_uint(a)));
    return p;
}

// C[t, e] = sum_k A[t,k] * W[e,k] — fp32, Eigen-blocked accumulation order:
// c = ((0 + S_0) + S_1) + ... ; S_b = ascending-k fma partial over kc=320 block
// (last block = 128). BIT-EXACT match to XLA:CPU Eigen gemm — do not reorder.
//
// BM=64 x BN=32 -> 2048 CTAs of 128 threads at OCCUPANCY 7 (1036 slots):
// two clean waves (2048/1036 = 1.98, ~1% drain waste) AND 28 warps/SM
// (7/SMSP) for latency hiding — fixes R8's 13.5% tail without the low-warp
// curse that killed R9-R12. Per thread 8m x 2n (n-packed): 8 FFMA2 + 8 dup +
// 3 LDS per thread-k -> FMA-pipe-bound with 25% issue slack.
// Grid m-fastest: concurrent n-columns share the same A m-rows in L2.
__global__ __launch_bounds__(128, 7)
void moe_gemm_kernel(const float* __restrict__ A,
                     const float* __restrict__ W,
                     float* __restrict__ C, int T) {
    __shared__ float As[2][BK][BM];
    __shared__ float Bs[2][BK][BN];

    const int tid = threadIdx.x;
    const int tx = tid & 15;   // n: 2 experts per thread (16*2 = 32)
    const int ty = tid >> 4;   // m: 8 tokens per thread  (8*8 = 64)
    const int m0 = blockIdx.x * BM;   // grid.x = 256 m-tiles (fastest)
    const int n0 = blockIdx.y * BN;   // grid.y = 8 n-tiles

    // A loader: 2 threads per row, 8 floats (2x float4) each  (64 rows x 16 k)
    const int alr = tid >> 1;
    const int alc = (tid & 1) * 8;
    const float* Abase = A + (size_t)(m0 + alr) * K_DIM + alc;
    // B loader: 4 threads per row, one float4 each  (32 rows x 16 k)
    const int blr = tid >> 2;
    const int blc = (tid & 3) * 4;
    const float* Wbase = W + (size_t)(n0 + blr) * K_DIM + blc;

    unsigned long long acc[8], bac[8];   // [m], each packs experts (2tx, 2tx+1)
#pragma unroll
    for (int i = 0; i < 8; ++i) { acc[i] = 0ull; bac[i] = 0ull; }

    float4 aP0 = *reinterpret_cast<const float4*>(Abase);
    float4 aP1 = *reinterpret_cast<const float4*>(Abase + 4);
    float4 bP  = *reinterpret_cast<const float4*>(Wbase);

    const int nIter = K_DIM / BK;  // 448
    for (int kt = 0; kt < nIter; ++kt) {
        const int buf = kt & 1;
        As[buf][alc + 0][alr] = aP0.x; As[buf][alc + 1][alr] = aP0.y;
        As[buf][alc + 2][alr] = aP0.z; As[buf][alc + 3][alr] = aP0.w;
        As[buf][alc + 4][alr] = aP1.x; As[buf][alc + 5][alr] = aP1.y;
        As[buf][alc + 6][alr] = aP1.z; As[buf][alc + 7][alr] = aP1.w;
        Bs[buf][blc + 0][blr] = bP.x;  Bs[buf][blc + 1][blr] = bP.y;
        Bs[buf][blc + 2][blr] = bP.z;  Bs[buf][blc + 3][blr] = bP.w;
        __syncthreads();

        // prefetch next tile from global (hidden by 28 warps/SM)
        if (kt + 1 < nIter) {
            const float* an = Abase + (size_t)(kt + 1) * BK;
            const float* wn = Wbase + (size_t)(kt + 1) * BK;
            aP0 = *reinterpret_cast<const float4*>(an);
            aP1 = *reinterpret_cast<const float4*>(an + 4);
            bP  = *reinterpret_cast<const float4*>(wn);
        }

#pragma unroll
        for (int k = 0; k < BK; ++k) {
            float4 a0 = *reinterpret_cast<const float4*>(&As[buf][k][ty * 8]);
            float4 a1 = *reinterpret_cast<const float4*>(&As[buf][k][ty * 8 + 4]);
            unsigned long long pb =
                *reinterpret_cast<const unsigned long long*>(&Bs[buf][k][tx * 2]);
            float av[8] = {a0.x, a0.y, a0.z, a0.w, a1.x, a1.y, a1.z, a1.w};
#pragma unroll
            for (int i = 0; i < 8; ++i)
                bac[i] = ffma2(dup_f32(av[i]), pb, bac[i]);
        }

        // Eigen kc=320 block boundary: c += S_b; S_b = 0
        if (((kt + 1) % KC_TILES) == 0) {
#pragma unroll
            for (int i = 0; i < 8; ++i) {
                acc[i] = fadd2(acc[i], bac[i]);
                bac[i] = 0ull;
            }
        }
    }

    // final (remainder 128-wide) block flush
#pragma unroll
    for (int i = 0; i < 8; ++i) acc[i] = fadd2(acc[i], bac[i]);

    // epilogue: acc[i] = (e0,e1) for token m0+ty*8+i, experts n0+tx*2, +1
#pragma unroll
    for (int i = 0; i < 8; ++i) {
        int m = m0 + ty * 8 + i;
        float2 v = *reinterpret_cast<float2*>(&acc[i]);
        *reinterpret_cast<float2*>(C + (size_t)m * E_DIM + n0 + tx * 2) = v;
    }
}

// XLA EmitFastTanh replica — UNFUSED mul/add Horner (CPU LLVM does not
// contract), IEEE fdiv, clamp +-7.90531110763549805, |x|<0.0004 -> x.
__device__ __forceinline__ float xla_tanhf_nofma(float x) {
    float xc = fminf(fmaxf(x, -7.90531110763549805f), 7.90531110763549805f);
    float x2 = __fmul_rn(xc, xc);
    float np = -2.76076847742355e-16f;
    np = __fadd_rn(__fmul_rn(x2, np),  2.00018790482477e-13f);
    np = __fadd_rn(__fmul_rn(x2, np), -8.60467152213735e-11f);
    np = __fadd_rn(__fmul_rn(x2, np),  5.12229709037114e-08f);
    np = __fadd_rn(__fmul_rn(x2, np),  1.48572235717979e-05f);
    np = __fadd_rn(__fmul_rn(x2, np),  6.37261928875436e-04f);
    np = __fadd_rn(__fmul_rn(x2, np),  4.89352455891786e-03f);
    float num = __fmul_rn(xc, np);
    float dp = 1.19825839466702e-06f;
    dp = __fadd_rn(__fmul_rn(x2, dp), 1.18534705686654e-04f);
    dp = __fadd_rn(__fmul_rn(x2, dp), 2.26843463243900e-03f);
    dp = __fadd_rn(__fmul_rn(x2, dp), 4.89352518554385e-03f);
    float r = __fdiv_rn(num, dp);
    return (fabsf(x) < 0.0004f) ? x : r;
}

// XLA logistic: 0.5 + 0.5 * tanh(0.5 * x), unfused.
__device__ __forceinline__ float sigmoid_xla(float x) {
    float t = xla_tanhf_nofma(__fmul_rn(0.5f, x));
    return __fadd_rn(0.5f, __fmul_rn(0.5f, t));
}

// one warp per token
__global__ void moe_router_kernel(const float* __restrict__ logits,
                                  float* __restrict__ outW,
                                  float* __restrict__ outI, int T) {
    const unsigned FULL = 0xFFFFFFFFu;
    int warp = (blockIdx.x * blockDim.x + threadIdx.x) >> 5;
    int lane = threadIdx.x & 31;
    if (warp >= T) return;

    const float* row = logits + (size_t)warp * E_DIM;
    float4 v0 = *reinterpret_cast<const float4*>(row + lane * 8);
    float4 v1 = *reinterpret_cast<const float4*>(row + lane * 8 + 4);

    float s[8];
    s[0] = sigmoid_xla(v0.x); s[1] = sigmoid_xla(v0.y);
    s[2] = sigmoid_xla(v0.z); s[3] = sigmoid_xla(v0.w);
    s[4] = sigmoid_xla(v1.x); s[5] = sigmoid_xla(v1.y);
    s[6] = sigmoid_xla(v1.z); s[7] = sigmoid_xla(v1.w);

    // group sum over 32 experts (butterfly tree)
    float f[8];
#pragma unroll
    for (int j = 0; j < 8; ++j)
        f[j] = s[j] + __shfl_xor_sync(FULL, s[j], 2);
    float g[8];
#pragma unroll
    for (int j = 0; j < 8; ++j)
        g[j] = f[j] + __shfl_xor_sync(FULL, f[j], 1);
    float h0 = g[0] + g[4];
    float h1 = g[1] + g[5];
    float h2 = g[2] + g[6];
    float h3 = g[3] + g[7];
    float p0 = h0 + h2;
    float p1 = h1 + h3;
    float mygs = p0 + p1;     // group sum for group (lane>>2)
    int myg = lane >> 2;

    // rank of my group among 8 groups (ties -> lower index, jax top_k)
    int rank = 0;
#pragma unroll
    for (int h = 0; h < 8; ++h) {
        float gh = __shfl_sync(FULL, mygs, h * 4);
        if (h != myg && (gh > mygs || (gh == mygs && h < myg))) rank++;
    }
    bool sel = (rank < 4);

    float ms[8];
#pragma unroll
    for (int j = 0; j < 8; ++j) ms[j] = sel ? s[j] : 0.0f;

    float topv[8];
    int topi[8];
#pragma unroll
    for (int it = 0; it < 8; ++it) {
        float bv = -1.0f;
        int bi = 0;
#pragma unroll
        for (int j = 0; j < 8; ++j) {
            if (ms[j] > bv) { bv = ms[j]; bi = lane * 8 + j; }
        }
#pragma unroll
        for (int off = 16; off; off >>= 1) {
            float ov = __shfl_xor_sync(FULL, bv, off);
            int oi = __shfl_xor_sync(FULL, bi, off);
            if (ov > bv || (ov == bv && oi < bi)) { bv = ov; bi = oi; }
        }
        topv[it] = bv;
        topi[it] = bi;
        if ((bi >> 3) == lane) ms[bi & 7] = -1.0f;
    }

    float denom = 0.f;
#pragma unroll
    for (int it = 0; it < 8; ++it) denom += topv[it];
    denom = fmaxf(denom, 1e-12f);

    if (lane < 8) {
        outW[(size_t)warp * 8 + lane] = __fdiv_rn(topv[lane], denom);
        outI[(size_t)warp * 8 + lane] = (float)topi[lane];
    }
}

extern "C" void kernel_launch(void* const* d_in, const int* in_sizes, int n_in,
                              void* d_out, int out_size) {
    const float* H = (const float*)d_in[0];   // [T, 7168] fp32
    const float* W = (const float*)d_in[1];   // [256, 7168] fp32
    float* out = (float*)d_out;

    int T = in_sizes[0] / K_DIM;

    // output layout: [T*8 weights][T*8 indices][T*256 logits]
    float* outW = out;
    float* outI = out + (size_t)T * 8;
    float* logits = out + (size_t)T * 16;

    // m-fastest: CTAs sharing the same m-rows (different n) run concurrently
    // -> A fetched ~once per wave, W (7MB) permanently L2-resident
    dim3 grid(T / BM, E_DIM / BN);
    moe_gemm_kernel<<<grid, 128>>>(H, W, logits, T);

    int warps = T;
    int threads = 256;
    int blocks = (warps * 32 + threads - 1) / threads;
    moe_router_kernel<<<blocks, threads>>>(logits, outW, outI, T);
}